// round 11
// baseline (speedup 1.0000x reference)
#include <cuda_runtime.h>
#include <cuda_bf16.h>
#include <math.h>
#include <stdint.h>

#define N_NODES  50000
#define N_EDGES  800000
#define N_GRAPHS 512
#define IN_DIM   128
#define HID      256
#define OUT_DIM  40

// ---------------- scratch (device globals; no allocation allowed) ----------------
__device__ float g_hA [(size_t)N_NODES * HID];
__device__ float g_hB [(size_t)N_NODES * HID];
__device__ __nv_bfloat16 g_AH[(size_t)N_NODES * HID];
__device__ __nv_bfloat16 g_AL[(size_t)N_NODES * HID];
__device__ __nv_bfloat16 g_TH[(size_t)N_NODES * HID];
__device__ __nv_bfloat16 g_TL[(size_t)N_NODES * HID];
#define W_TOTAL 491520   // 256x128 + 7x 256x256, transposed K-major
__device__ __nv_bfloat16 g_WH[W_TOTAL];
__device__ __nv_bfloat16 g_WL[W_TOTAL];
__device__ int   g_deg[N_NODES];
__device__ int   g_rowptr[N_NODES + 1];
__device__ int   g_cursor[N_NODES];
__device__ int   g_eidx[N_EDGES];
__device__ float g_pool[N_GRAPHS * HID];

// ---------------- helpers ----------------
__device__ __forceinline__ uint32_t pkbf(float a, float b) {
    __nv_bfloat162 t = __floats2bfloat162_rn(a, b);
    uint32_t u; memcpy(&u, &t, 4); return u;
}
__device__ __forceinline__ void split2(float v, float& h, float& l) {
    h = __bfloat162float(__float2bfloat16(v));
    l = v - h;
}
__device__ __forceinline__ uint32_t s2u(const void* p) {
    uint32_t a;
    asm("{ .reg .u64 t; cvta.to.shared.u64 t, %1; cvt.u32.u64 %0, t; }"
        : "=r"(a) : "l"(p));
    return a;
}
__device__ __forceinline__ void ldmx4(uint32_t* r, uint32_t addr) {
    asm volatile("ldmatrix.sync.aligned.m8n8.x4.shared.b16 {%0,%1,%2,%3}, [%4];"
                 : "=r"(r[0]), "=r"(r[1]), "=r"(r[2]), "=r"(r[3]) : "r"(addr));
}
__device__ __forceinline__ void mma_bf16(float* c, const uint32_t* a, const uint32_t* b) {
    asm volatile(
        "mma.sync.aligned.m16n8k16.row.col.f32.bf16.bf16.f32 "
        "{%0,%1,%2,%3}, {%4,%5,%6,%7}, {%8,%9}, {%0,%1,%2,%3};"
        : "+f"(c[0]), "+f"(c[1]), "+f"(c[2]), "+f"(c[3])
        : "r"(a[0]), "r"(a[1]), "r"(a[2]), "r"(a[3]), "r"(b[0]), "r"(b[1]));
}
__device__ __forceinline__ void cpa16(uint32_t dst, const void* src, uint32_t vsz) {
    asm volatile("cp.async.cg.shared.global [%0], [%1], 16, %2;"
                 :: "r"(dst), "l"(src), "r"(vsz));
}
#define CP_COMMIT() asm volatile("cp.async.commit_group;" ::: "memory")
#define CP_WAIT0()  asm volatile("cp.async.wait_group 0;" ::: "memory")

// ---------------- CSR build ----------------
__global__ void hist_k(const int* __restrict__ dst) {
    int e = blockIdx.x * blockDim.x + threadIdx.x;
    if (e < N_EDGES) atomicAdd(&g_deg[dst[e]], 1);
}

__global__ void scan_k() {
    __shared__ int buf[1024];
    __shared__ int carry;
    int tid = threadIdx.x;
    if (tid == 0) carry = 0;
    __syncthreads();
    for (int base = 0; base < N_NODES; base += 1024) {
        int v = (base + tid < N_NODES) ? g_deg[base + tid] : 0;
        buf[tid] = v;
        __syncthreads();
        for (int off = 1; off < 1024; off <<= 1) {
            int t = (tid >= off) ? buf[tid - off] : 0;
            __syncthreads();
            buf[tid] += t;
            __syncthreads();
        }
        int c0 = carry;
        if (base + tid < N_NODES) g_rowptr[base + tid] = buf[tid] - v + c0;
        __syncthreads();
        if (tid == 0) carry += buf[1023];
        __syncthreads();
    }
    if (tid == 0) g_rowptr[N_NODES] = carry;
}

__global__ void fill_k(const int* __restrict__ src, const int* __restrict__ dst) {
    int e = blockIdx.x * blockDim.x + threadIdx.x;
    if (e < N_EDGES) {
        int d = dst[e];
        int p = atomicAdd(&g_cursor[d], 1);
        g_eidx[p] = src[e];
    }
}

// ---------------- fused weight pre-split + transpose (all 8 matrices) ----------------
__global__ void wt_all(const float* __restrict__ w1a, const float* __restrict__ w2a,
                       const float* __restrict__ w1r, const float* __restrict__ w2r,
                       __nv_bfloat16* __restrict__ dH, __nv_bfloat16* __restrict__ dL) {
    int idx = blockIdx.x * blockDim.x + threadIdx.x;
    if (idx >= W_TOTAL) return;
    const float* W; int K, loc;
    if (idx < 32768)       { W = w1a; K = 128; loc = idx; }
    else if (idx < 98304)  { W = w2a; K = 256; loc = idx - 32768; }
    else if (idx < 294912) { int r = idx - 98304;  W = w1r + (r >> 16) * 65536; K = 256; loc = r & 65535; }
    else                   { int r = idx - 294912; W = w2r + (r >> 16) * 65536; K = 256; loc = r & 65535; }
    int n = loc / K, k = loc - n * K;
    float v = __ldg(&W[(size_t)k * HID + n]);
    float h, l; split2(v, h, l);
    dH[idx] = __float2bfloat16(h);
    dL[idx] = __float2bfloat16(l);
}

// ---------------- fused aggregation + GIN add + limb split (4-way MLP) ----------------
__global__ void aggf_k(const float* __restrict__ X, const float* __restrict__ epsp,
                       int D4, __nv_bfloat16* __restrict__ AH,
                       __nv_bfloat16* __restrict__ AL) {
    int gid  = blockIdx.x * blockDim.x + threadIdx.x;
    int node = gid / D4;
    int c    = gid - node * D4;
    int s = g_rowptr[node];
    int e = g_rowptr[node + 1];
    const float4* x4 = (const float4*)X;
    float4 a0 = make_float4(0.f, 0.f, 0.f, 0.f);
    float4 a1 = make_float4(0.f, 0.f, 0.f, 0.f);
    float4 a2 = make_float4(0.f, 0.f, 0.f, 0.f);
    float4 a3 = make_float4(0.f, 0.f, 0.f, 0.f);
    int j = s;
    for (; j + 3 < e; j += 4) {
        int s0 = g_eidx[j],     s1 = g_eidx[j + 1];
        int s2 = g_eidx[j + 2], s3 = g_eidx[j + 3];
        float4 v0 = __ldg(&x4[(size_t)s0 * D4 + c]);
        float4 v1 = __ldg(&x4[(size_t)s1 * D4 + c]);
        float4 v2 = __ldg(&x4[(size_t)s2 * D4 + c]);
        float4 v3 = __ldg(&x4[(size_t)s3 * D4 + c]);
        a0.x += v0.x; a0.y += v0.y; a0.z += v0.z; a0.w += v0.w;
        a1.x += v1.x; a1.y += v1.y; a1.z += v1.z; a1.w += v1.w;
        a2.x += v2.x; a2.y += v2.y; a2.z += v2.z; a2.w += v2.w;
        a3.x += v3.x; a3.y += v3.y; a3.z += v3.z; a3.w += v3.w;
    }
    for (; j < e; j++) {
        int s0 = g_eidx[j];
        float4 v0 = __ldg(&x4[(size_t)s0 * D4 + c]);
        a0.x += v0.x; a0.y += v0.y; a0.z += v0.z; a0.w += v0.w;
    }
    float alpha = 1.0f + __ldg(epsp);
    float4 xs = __ldg(&x4[(size_t)node * D4 + c]);
    float4 v;
    v.x = alpha * xs.x + ((a0.x + a1.x) + (a2.x + a3.x));
    v.y = alpha * xs.y + ((a0.y + a1.y) + (a2.y + a3.y));
    v.z = alpha * xs.z + ((a0.z + a1.z) + (a2.z + a3.z));
    v.w = alpha * xs.w + ((a0.w + a1.w) + (a2.w + a3.w));
    float h0,l0,h1,l1,h2,l2,h3,l3;
    split2(v.x,h0,l0); split2(v.y,h1,l1); split2(v.z,h2,l2); split2(v.w,h3,l3);
    size_t base = (size_t)node * (D4 * 4) + c * 4;
    *(uint2*)&AH[base] = make_uint2(pkbf(h0, h1), pkbf(h2, h3));
    *(uint2*)&AL[base] = make_uint2(pkbf(l0, l1), pkbf(l2, l3));
}

// ---------------- pipelined bf16 2-limb tensor GEMM (occ 2, 1 sync/tile) ----------------
#define KT 32
#define OAH 0u
#define OAL 10240u
#define OBH 20480u
#define OBL 30720u
#define STG 40960u
#define GSMEM (2 * STG)

template<bool EPI_LIMB, bool BN_OUT>
__global__ void __launch_bounds__(256, 2) gemm_p(
    const __nv_bfloat16* __restrict__ AH, const __nv_bfloat16* __restrict__ AL,
    const __nv_bfloat16* __restrict__ WH, const __nv_bfloat16* __restrict__ WL,
    const float* __restrict__ bias,
    const float* __restrict__ gamma, const float* __restrict__ beta,
    float* __restrict__ Cf, __nv_bfloat16* __restrict__ CH,
    __nv_bfloat16* __restrict__ CL,
    int N, int K, int M)
{
    extern __shared__ char smem[];
    uint32_t sb = s2u(smem);
    int tid = threadIdx.x;
    int lane = tid & 31;
    int wid  = tid >> 5;
    int warp_m = wid & 3;
    int warp_n = wid >> 2;
    int g  = lane >> 2;
    int tg = lane & 3;

    int rowBase = blockIdx.y * 128;
    int colBase = blockIdx.x * 128;

    int fr = tid >> 1;
    int fk = (tid & 1) * 16;
    bool avalid = (rowBase + fr) < N;
    size_t aBase = (size_t)(avalid ? (rowBase + fr) : 0) * K + fk;
    size_t bBase = (size_t)(colBase + fr) * K + fk;
    uint32_t avsz = avalid ? 16u : 0u;
    uint32_t aDst = fr * 80 + fk * 2;

#define ISSUE_FILL(stage, k0) do {                                      \
    uint32_t s_ = sb + (stage) * STG;                                   \
    const char* pAH = (const char*)(AH + aBase + (k0));                 \
    const char* pAL = (const char*)(AL + aBase + (k0));                 \
    cpa16(s_ + OAH + aDst,      pAH,      avsz);                        \
    cpa16(s_ + OAH + aDst + 16, pAH + 16, avsz);                        \
    cpa16(s_ + OAL + aDst,      pAL,      avsz);                        \
    cpa16(s_ + OAL + aDst + 16, pAL + 16, avsz);                        \
    const char* pBH = (const char*)(WH + bBase + (k0));                 \
    const char* pBL = (const char*)(WL + bBase + (k0));                 \
    cpa16(s_ + OBH + aDst,      pBH,      16u);                         \
    cpa16(s_ + OBH + aDst + 16, pBH + 16, 16u);                         \
    cpa16(s_ + OBL + aDst,      pBL,      16u);                         \
    cpa16(s_ + OBL + aDst + 16, pBL + 16, 16u);                         \
} while (0)

    float acc[2][8][4];
    #pragma unroll
    for (int mt = 0; mt < 2; mt++)
        #pragma unroll
        for (int nt = 0; nt < 8; nt++)
            #pragma unroll
            for (int q = 0; q < 4; q++) acc[mt][nt][q] = 0.f;

    uint32_t aRel[2];
    #pragma unroll
    for (int mt = 0; mt < 2; mt++) {
        int r = warp_m * 32 + mt * 16 + (lane & 15);
        int c = (lane >> 4) * 8;
        aRel[mt] = OAH + r * 80 + c * 2;
    }
    uint32_t bRel[4];
    #pragma unroll
    for (int ntp = 0; ntp < 4; ntp++) {
        int n = warp_n * 64 + ntp * 16 + (lane >> 4) * 8 + (lane & 7);
        int c = ((lane >> 3) & 1) * 8;
        bRel[ntp] = OBH + n * 80 + c * 2;
    }
    const uint32_t dL = OAL - OAH;

    ISSUE_FILL(0, 0);
    CP_COMMIT();

    const int nkt = K / KT;
    for (int kt = 0; kt < nkt; kt++) {
        CP_WAIT0();
        __syncthreads();
        // fill(kt+1) writes stage (kt+1)&1, last read by compute(kt-1),
        // which every warp finished before the sync above -> safe with ONE sync.
        if (kt + 1 < nkt) {
            ISSUE_FILL((kt + 1) & 1, (kt + 1) * KT);
            CP_COMMIT();
        }

        uint32_t stg = sb + (kt & 1) * STG;
        #pragma unroll
        for (int ksub = 0; ksub < 2; ksub++) {
            uint32_t koff = ksub * 32;
            uint32_t aH[2][4], aLr[2][4];
            #pragma unroll
            for (int mt = 0; mt < 2; mt++) {
                ldmx4(aH[mt],  stg + aRel[mt] + koff);
                ldmx4(aLr[mt], stg + aRel[mt] + koff + dL);
            }
            {
                uint32_t bH[8][2];
                #pragma unroll
                for (int ntp = 0; ntp < 4; ntp++) {
                    uint32_t t[4];
                    ldmx4(t, stg + bRel[ntp] + koff);
                    bH[2*ntp][0] = t[0]; bH[2*ntp][1] = t[1];
                    bH[2*ntp+1][0] = t[2]; bH[2*ntp+1][1] = t[3];
                }
                #pragma unroll
                for (int mt = 0; mt < 2; mt++)
                    #pragma unroll
                    for (int nt = 0; nt < 8; nt++)
                        mma_bf16(acc[mt][nt], aH[mt], bH[nt]);
                #pragma unroll
                for (int mt = 0; mt < 2; mt++)
                    #pragma unroll
                    for (int nt = 0; nt < 8; nt++)
                        mma_bf16(acc[mt][nt], aLr[mt], bH[nt]);
            }
            {
                uint32_t bL[8][2];
                #pragma unroll
                for (int ntp = 0; ntp < 4; ntp++) {
                    uint32_t t[4];
                    ldmx4(t, stg + bRel[ntp] + koff + dL);
                    bL[2*ntp][0] = t[0]; bL[2*ntp][1] = t[1];
                    bL[2*ntp+1][0] = t[2]; bL[2*ntp+1][1] = t[3];
                }
                #pragma unroll
                for (int mt = 0; mt < 2; mt++)
                    #pragma unroll
                    for (int nt = 0; nt < 8; nt++)
                        mma_bf16(acc[mt][nt], aH[mt], bL[nt]);
            }
        }
    }
#undef ISSUE_FILL

    // ---- epilogue ----
    const float bnmul = rsqrtf(1.0f + 1e-5f);
    #pragma unroll
    for (int nt = 0; nt < 8; nt++) {
        int col0 = colBase + warp_n * 64 + nt * 8 + 2 * tg;
        float b0 = __ldg(&bias[col0]);
        float b1 = __ldg(&bias[col0 + 1]);
        float g0 = 0.f, g1 = 0.f, be0 = 0.f, be1 = 0.f;
        if (BN_OUT) {
            g0 = __ldg(&gamma[col0]) * bnmul;     be0 = __ldg(&beta[col0]);
            g1 = __ldg(&gamma[col0 + 1]) * bnmul; be1 = __ldg(&beta[col0 + 1]);
        }
        #pragma unroll
        for (int mt = 0; mt < 2; mt++) {
            int r0 = rowBase + warp_m * 32 + mt * 16 + g;
            #pragma unroll
            for (int half = 0; half < 2; half++) {
                int row = r0 + half * 8;
                if (row < N) {
                    float v0 = fmaxf(acc[mt][nt][2 * half + 0] + b0, 0.f);
                    float v1 = fmaxf(acc[mt][nt][2 * half + 1] + b1, 0.f);
                    if (BN_OUT) { v0 = v0 * g0 + be0; v1 = v1 * g1 + be1; }
                    if (EPI_LIMB) {
                        float h0,l0,h1,l1;
                        split2(v0, h0, l0); split2(v1, h1, l1);
                        *(uint32_t*)&CH[(size_t)row * M + col0] = pkbf(h0, h1);
                        *(uint32_t*)&CL[(size_t)row * M + col0] = pkbf(l0, l1);
                    } else {
                        *(float2*)(Cf + (size_t)row * M + col0) = make_float2(v0, v1);
                    }
                }
            }
        }
    }
}

// ---------------- pooling ----------------
__device__ __forceinline__ int lbound(const int* a, int n, int v) {
    int lo = 0, hi = n;
    while (lo < hi) { int m = (lo + hi) >> 1; if (a[m] < v) lo = m + 1; else hi = m; }
    return lo;
}

__global__ void pool_k(const float* __restrict__ H, const int* __restrict__ batch) {
    int g = blockIdx.x;
    int t = threadIdx.x;
    __shared__ int ss, se;
    if (t == 0)  ss = lbound(batch, N_NODES, g);
    if (t == 32) se = lbound(batch, N_NODES, g + 1);
    __syncthreads();
    int start = ss, end = se;
    int c = t & 63, sub = t >> 6;
    const float4* h4 = (const float4*)H;
    float4 acc = make_float4(0.f, 0.f, 0.f, 0.f);
    for (int i = start + sub; i < end; i += 4) {
        float4 v = h4[(size_t)i * 64 + c];
        acc.x += v.x; acc.y += v.y; acc.z += v.z; acc.w += v.w;
    }
    __shared__ float4 red[256];
    red[t] = acc;
    __syncthreads();
    if (sub == 0) {
        float4 a = red[c], b = red[c + 64], c2 = red[c + 128], d = red[c + 192];
        int cnt = end - start;
        float inv = 1.0f / (float)(cnt > 1 ? cnt : 1);
        float4 o;
        o.x = (a.x + b.x + c2.x + d.x) * inv;
        o.y = (a.y + b.y + c2.y + d.y) * inv;
        o.z = (a.z + b.z + c2.z + d.z) * inv;
        o.w = (a.w + b.w + c2.w + d.w) * inv;
        ((float4*)g_pool)[g * 64 + c] = o;
    }
}

// ---------------- final MLP + log_softmax ----------------
__global__ void final_k(const float* __restrict__ lw1, const float* __restrict__ lb1,
                        const float* __restrict__ lw2, const float* __restrict__ lb2,
                        float* __restrict__ out)
{
    int g = blockIdx.x, t = threadIdx.x;
    __shared__ float p[HID], o1[HID], o2[OUT_DIM];
    __shared__ float s_m, s_l;
    p[t] = g_pool[g * HID + t];
    __syncthreads();
    float acc = __ldg(&lb1[t]);
    for (int k = 0; k < HID; k++) acc = fmaf(p[k], __ldg(&lw1[k * HID + t]), acc);
    o1[t] = fmaxf(acc, 0.f);
    __syncthreads();
    if (t < OUT_DIM) {
        float a = __ldg(&lb2[t]);
        for (int k = 0; k < HID; k++) a = fmaf(o1[k], __ldg(&lw2[k * OUT_DIM + t]), a);
        o2[t] = a;
    }
    __syncthreads();
    if (t == 0) {
        float m = -1e30f;
        for (int j = 0; j < OUT_DIM; j++) m = fmaxf(m, o2[j]);
        float s = 0.f;
        for (int j = 0; j < OUT_DIM; j++) s += expf(o2[j] - m);
        s_m = m; s_l = logf(s);
    }
    __syncthreads();
    if (t < OUT_DIM) out[g * OUT_DIM + t] = o2[t] - s_m - s_l;
}

// ---------------- launcher ----------------
extern "C" void kernel_launch(void* const* d_in, const int* in_sizes, int n_in,
                              void* d_out, int out_size)
{
    const float* x    = (const float*)d_in[0];
    const int*   ei   = (const int*)  d_in[1];
    const int*   batch= (const int*)  d_in[2];
    const float* w1a  = (const float*)d_in[3];
    const float* b1a  = (const float*)d_in[4];
    const float* w2a  = (const float*)d_in[5];
    const float* b2a  = (const float*)d_in[6];
    const float* ga   = (const float*)d_in[7];
    const float* bba  = (const float*)d_in[8];
    const float* eps0 = (const float*)d_in[9];
    const float* w1r  = (const float*)d_in[10];
    const float* b1r  = (const float*)d_in[11];
    const float* w2r  = (const float*)d_in[12];
    const float* b2r  = (const float*)d_in[13];
    const float* gr   = (const float*)d_in[14];
    const float* br   = (const float*)d_in[15];
    const float* epsr = (const float*)d_in[16];
    const float* lw1  = (const float*)d_in[17];
    const float* lb1  = (const float*)d_in[18];
    const float* lw2  = (const float*)d_in[19];
    const float* lb2  = (const float*)d_in[20];
    float* out = (float*)d_out;

    const int* src = ei;
    const int* dst = ei + N_EDGES;

    void *hA_p, *hB_p, *AH_p, *AL_p, *TH_p, *TL_p, *WH_p, *WL_p;
    void *deg_p, *rp_p, *cur_p;
    cudaGetSymbolAddress(&hA_p, g_hA);
    cudaGetSymbolAddress(&hB_p, g_hB);
    cudaGetSymbolAddress(&AH_p, g_AH);
    cudaGetSymbolAddress(&AL_p, g_AL);
    cudaGetSymbolAddress(&TH_p, g_TH);
    cudaGetSymbolAddress(&TL_p, g_TL);
    cudaGetSymbolAddress(&WH_p, g_WH);
    cudaGetSymbolAddress(&WL_p, g_WL);
    cudaGetSymbolAddress(&deg_p, g_deg);
    cudaGetSymbolAddress(&rp_p,  g_rowptr);
    cudaGetSymbolAddress(&cur_p, g_cursor);

    float* hA = (float*)hA_p;
    float* hB = (float*)hB_p;
    __nv_bfloat16* AH = (__nv_bfloat16*)AH_p;
    __nv_bfloat16* AL = (__nv_bfloat16*)AL_p;
    __nv_bfloat16* TH = (__nv_bfloat16*)TH_p;
    __nv_bfloat16* TL = (__nv_bfloat16*)TL_p;
    __nv_bfloat16* WH = (__nv_bfloat16*)WH_p;
    __nv_bfloat16* WL = (__nv_bfloat16*)WL_p;

    static bool attr_done = false;
    if (!attr_done) {
        cudaFuncSetAttribute(gemm_p<true,  false>,
                             cudaFuncAttributeMaxDynamicSharedMemorySize, GSMEM);
        cudaFuncSetAttribute(gemm_p<false, true>,
                             cudaFuncAttributeMaxDynamicSharedMemorySize, GSMEM);
        attr_done = true;
    }

    // --- weight pre-split/transpose (single fused launch) ---
    wt_all<<<(W_TOTAL + 255) / 256, 256>>>(w1a, w2a, w1r, w2r, WH, WL);

    // --- CSR build ---
    cudaMemsetAsync(deg_p, 0, N_NODES * sizeof(int));
    hist_k<<<(N_EDGES + 255) / 256, 256>>>(dst);
    scan_k<<<1, 1024>>>();
    cudaMemcpyAsync(cur_p, rp_p, N_NODES * sizeof(int), cudaMemcpyDeviceToDevice);
    fill_k<<<(N_EDGES + 255) / 256, 256>>>(src, dst);

    const int OW1A = 0;
    const int OW2A = 32768;
    const int OW1R = 98304;
    const int OW2R = 294912;

    dim3 grid(HID / 128, (N_NODES + 127) / 128);   // (2, 391)

    // --- layer 1 ---
    aggf_k<<<(N_NODES * 32) / 256, 256>>>(x, eps0, IN_DIM / 4, AH, AL);
    gemm_p<true,  false><<<grid, 256, GSMEM>>>(AH, AL, WH + OW1A, WL + OW1A,
                                               b1a, nullptr, nullptr,
                                               nullptr, TH, TL, N_NODES, IN_DIM, HID);
    gemm_p<false, true ><<<grid, 256, GSMEM>>>(TH, TL, WH + OW2A, WL + OW2A,
                                               b2a, ga, bba,
                                               hA, nullptr, nullptr, N_NODES, HID, HID);

    // --- layers 2..4 ---
    const float* hin = hA;
    float* hout = hB;
    for (int i = 0; i < 3; i++) {
        aggf_k<<<(N_NODES * 64) / 256, 256>>>(hin, epsr + i, HID / 4, AH, AL);
        gemm_p<true,  false><<<grid, 256, GSMEM>>>(AH, AL,
                                                   WH + OW1R + i * 65536,
                                                   WL + OW1R + i * 65536,
                                                   b1r + i * HID, nullptr, nullptr,
                                                   nullptr, TH, TL, N_NODES, HID, HID);
        gemm_p<false, true ><<<grid, 256, GSMEM>>>(TH, TL,
                                                   WH + OW2R + i * 65536,
                                                   WL + OW2R + i * 65536,
                                                   b2r + i * HID,
                                                   gr + i * HID, br + i * HID,
                                                   hout, nullptr, nullptr,
                                                   N_NODES, HID, HID);
        const float* t2 = hin; hin = hout; hout = (float*)t2;
    }

    // --- pooling + head ---
    pool_k<<<N_GRAPHS, 256>>>(hin, batch);
    final_k<<<N_GRAPHS, 256>>>(lw1, lb1, lw2, lb2, out);
}

// round 12
// speedup vs baseline: 1.0973x; 1.0973x over previous
#include <cuda_runtime.h>
#include <cuda_bf16.h>
#include <math.h>
#include <stdint.h>

#define N_NODES  50000
#define N_EDGES  800000
#define N_GRAPHS 512
#define IN_DIM   128
#define HID      256
#define OUT_DIM  40

// ---------------- scratch (device globals; no allocation allowed) ----------------
__device__ float g_hA [(size_t)N_NODES * HID];
__device__ float g_hB [(size_t)N_NODES * HID];
__device__ __nv_bfloat16 g_AH[(size_t)N_NODES * HID];
__device__ __nv_bfloat16 g_AL[(size_t)N_NODES * HID];
__device__ __nv_bfloat16 g_TH[(size_t)N_NODES * HID];
__device__ __nv_bfloat16 g_TL[(size_t)N_NODES * HID];
#define W_TOTAL 491520   // 256x128 + 7x 256x256, transposed K-major
__device__ __nv_bfloat16 g_WH[W_TOTAL];
__device__ __nv_bfloat16 g_WL[W_TOTAL];
__device__ int   g_deg[N_NODES];
__device__ int   g_rowptr[N_NODES + 1];
__device__ int   g_cursor[N_NODES];
__device__ int   g_eidx[N_EDGES];
__device__ float g_pool[N_GRAPHS * HID];

// ---------------- helpers ----------------
__device__ __forceinline__ uint32_t pkbf(float a, float b) {
    __nv_bfloat162 t = __floats2bfloat162_rn(a, b);
    uint32_t u; memcpy(&u, &t, 4); return u;
}
__device__ __forceinline__ void split2(float v, float& h, float& l) {
    h = __bfloat162float(__float2bfloat16(v));
    l = v - h;
}
__device__ __forceinline__ uint32_t s2u(const void* p) {
    uint32_t a;
    asm("{ .reg .u64 t; cvta.to.shared.u64 t, %1; cvt.u32.u64 %0, t; }"
        : "=r"(a) : "l"(p));
    return a;
}
__device__ __forceinline__ void ldmx4(uint32_t* r, uint32_t addr) {
    asm volatile("ldmatrix.sync.aligned.m8n8.x4.shared.b16 {%0,%1,%2,%3}, [%4];"
                 : "=r"(r[0]), "=r"(r[1]), "=r"(r[2]), "=r"(r[3]) : "r"(addr));
}
__device__ __forceinline__ void mma_bf16(float* c, const uint32_t* a, const uint32_t* b) {
    asm volatile(
        "mma.sync.aligned.m16n8k16.row.col.f32.bf16.bf16.f32 "
        "{%0,%1,%2,%3}, {%4,%5,%6,%7}, {%8,%9}, {%0,%1,%2,%3};"
        : "+f"(c[0]), "+f"(c[1]), "+f"(c[2]), "+f"(c[3])
        : "r"(a[0]), "r"(a[1]), "r"(a[2]), "r"(a[3]), "r"(b[0]), "r"(b[1]));
}
__device__ __forceinline__ void cpa16(uint32_t dst, const void* src, uint32_t vsz) {
    asm volatile("cp.async.cg.shared.global [%0], [%1], 16, %2;"
                 :: "r"(dst), "l"(src), "r"(vsz));
}
#define CP_COMMIT() asm volatile("cp.async.commit_group;" ::: "memory")
#define CP_WAIT1()  asm volatile("cp.async.wait_group 1;" ::: "memory")
#define CP_WAIT0()  asm volatile("cp.async.wait_group 0;" ::: "memory")

// ---------------- CSR build ----------------
__global__ void hist_k(const int* __restrict__ dst) {
    int e = blockIdx.x * blockDim.x + threadIdx.x;
    if (e < N_EDGES) atomicAdd(&g_deg[dst[e]], 1);
}

__global__ void scan_k() {
    __shared__ int buf[1024];
    __shared__ int carry;
    int tid = threadIdx.x;
    if (tid == 0) carry = 0;
    __syncthreads();
    for (int base = 0; base < N_NODES; base += 1024) {
        int v = (base + tid < N_NODES) ? g_deg[base + tid] : 0;
        buf[tid] = v;
        __syncthreads();
        for (int off = 1; off < 1024; off <<= 1) {
            int t = (tid >= off) ? buf[tid - off] : 0;
            __syncthreads();
            buf[tid] += t;
            __syncthreads();
        }
        int c0 = carry;
        if (base + tid < N_NODES) g_rowptr[base + tid] = buf[tid] - v + c0;
        __syncthreads();
        if (tid == 0) carry += buf[1023];
        __syncthreads();
    }
    if (tid == 0) g_rowptr[N_NODES] = carry;
}

__global__ void fill_k(const int* __restrict__ src, const int* __restrict__ dst) {
    int e = blockIdx.x * blockDim.x + threadIdx.x;
    if (e < N_EDGES) {
        int d = dst[e];
        int p = atomicAdd(&g_cursor[d], 1);
        g_eidx[p] = src[e];
    }
}

// ---------------- fused weight pre-split + transpose (all 8 matrices) ----------------
__global__ void wt_all(const float* __restrict__ w1a, const float* __restrict__ w2a,
                       const float* __restrict__ w1r, const float* __restrict__ w2r,
                       __nv_bfloat16* __restrict__ dH, __nv_bfloat16* __restrict__ dL) {
    int idx = blockIdx.x * blockDim.x + threadIdx.x;
    if (idx >= W_TOTAL) return;
    const float* W; int K, loc;
    if (idx < 32768)       { W = w1a; K = 128; loc = idx; }
    else if (idx < 98304)  { W = w2a; K = 256; loc = idx - 32768; }
    else if (idx < 294912) { int r = idx - 98304;  W = w1r + (r >> 16) * 65536; K = 256; loc = r & 65535; }
    else                   { int r = idx - 294912; W = w2r + (r >> 16) * 65536; K = 256; loc = r & 65535; }
    int n = loc / K, k = loc - n * K;
    float v = __ldg(&W[(size_t)k * HID + n]);
    float h, l; split2(v, h, l);
    dH[idx] = __float2bfloat16(h);
    dL[idx] = __float2bfloat16(l);
}

// ---------------- fused aggregation + GIN add + limb split (2-way, round-10) ------
__global__ void aggf_k(const float* __restrict__ X, const float* __restrict__ epsp,
                       int D4, __nv_bfloat16* __restrict__ AH,
                       __nv_bfloat16* __restrict__ AL) {
    int gid  = blockIdx.x * blockDim.x + threadIdx.x;
    int node = gid / D4;
    int c    = gid - node * D4;
    int s = g_rowptr[node];
    int e = g_rowptr[node + 1];
    const float4* x4 = (const float4*)X;
    float4 acc0 = make_float4(0.f, 0.f, 0.f, 0.f);
    float4 acc1 = make_float4(0.f, 0.f, 0.f, 0.f);
    int j = s;
    for (; j + 1 < e; j += 2) {
        int s0 = g_eidx[j];
        int s1 = g_eidx[j + 1];
        float4 v0 = __ldg(&x4[(size_t)s0 * D4 + c]);
        float4 v1 = __ldg(&x4[(size_t)s1 * D4 + c]);
        acc0.x += v0.x; acc0.y += v0.y; acc0.z += v0.z; acc0.w += v0.w;
        acc1.x += v1.x; acc1.y += v1.y; acc1.z += v1.z; acc1.w += v1.w;
    }
    if (j < e) {
        int s0 = g_eidx[j];
        float4 v0 = __ldg(&x4[(size_t)s0 * D4 + c]);
        acc0.x += v0.x; acc0.y += v0.y; acc0.z += v0.z; acc0.w += v0.w;
    }
    float alpha = 1.0f + __ldg(epsp);
    float4 xs = __ldg(&x4[(size_t)node * D4 + c]);
    float4 v;
    v.x = alpha * xs.x + acc0.x + acc1.x;
    v.y = alpha * xs.y + acc0.y + acc1.y;
    v.z = alpha * xs.z + acc0.z + acc1.z;
    v.w = alpha * xs.w + acc0.w + acc1.w;
    float h0,l0,h1,l1,h2,l2,h3,l3;
    split2(v.x,h0,l0); split2(v.y,h1,l1); split2(v.z,h2,l2); split2(v.w,h3,l3);
    size_t base = (size_t)node * (D4 * 4) + c * 4;
    *(uint2*)&AH[base] = make_uint2(pkbf(h0, h1), pkbf(h2, h3));
    *(uint2*)&AL[base] = make_uint2(pkbf(l0, l1), pkbf(l2, l3));
}

// ---------------- pipelined bf16 2-limb tensor GEMM (occ 2, round-10 pipeline, K templated) ----
#define KT 32
#define OAH 0u
#define OAL 10240u
#define OBH 20480u
#define OBL 30720u
#define STG 40960u
#define GSMEM (2 * STG)

template<int KK, bool EPI_LIMB, bool BN_OUT>
__global__ void __launch_bounds__(256, 2) gemm_p(
    const __nv_bfloat16* __restrict__ AH, const __nv_bfloat16* __restrict__ AL,
    const __nv_bfloat16* __restrict__ WH, const __nv_bfloat16* __restrict__ WL,
    const float* __restrict__ bias,
    const float* __restrict__ gamma, const float* __restrict__ beta,
    float* __restrict__ Cf, __nv_bfloat16* __restrict__ CH,
    __nv_bfloat16* __restrict__ CL,
    int N, int M)
{
    extern __shared__ char smem[];
    uint32_t sb = s2u(smem);
    int tid = threadIdx.x;
    int lane = tid & 31;
    int wid  = tid >> 5;
    int warp_m = wid & 3;
    int warp_n = wid >> 2;
    int g  = lane >> 2;
    int tg = lane & 3;

    int rowBase = blockIdx.y * 128;
    int colBase = blockIdx.x * 128;

    int fr = tid >> 1;
    int fk = (tid & 1) * 16;
    bool avalid = (rowBase + fr) < N;
    size_t aBase = (size_t)(avalid ? (rowBase + fr) : 0) * KK + fk;
    size_t bBase = (size_t)(colBase + fr) * KK + fk;
    uint32_t avsz = avalid ? 16u : 0u;
    uint32_t aDst = fr * 80 + fk * 2;

#define ISSUE_FILL(stage, k0) do {                                      \
    uint32_t s_ = sb + (stage) * STG;                                   \
    const char* pAH = (const char*)(AH + aBase + (k0));                 \
    const char* pAL = (const char*)(AL + aBase + (k0));                 \
    cpa16(s_ + OAH + aDst,      pAH,      avsz);                        \
    cpa16(s_ + OAH + aDst + 16, pAH + 16, avsz);                        \
    cpa16(s_ + OAL + aDst,      pAL,      avsz);                        \
    cpa16(s_ + OAL + aDst + 16, pAL + 16, avsz);                        \
    const char* pBH = (const char*)(WH + bBase + (k0));                 \
    const char* pBL = (const char*)(WL + bBase + (k0));                 \
    cpa16(s_ + OBH + aDst,      pBH,      16u);                         \
    cpa16(s_ + OBH + aDst + 16, pBH + 16, 16u);                         \
    cpa16(s_ + OBL + aDst,      pBL,      16u);                         \
    cpa16(s_ + OBL + aDst + 16, pBL + 16, 16u);                         \
} while (0)

    float acc[2][8][4];
    #pragma unroll
    for (int mt = 0; mt < 2; mt++)
        #pragma unroll
        for (int nt = 0; nt < 8; nt++)
            #pragma unroll
            for (int q = 0; q < 4; q++) acc[mt][nt][q] = 0.f;

    uint32_t aRel[2];
    #pragma unroll
    for (int mt = 0; mt < 2; mt++) {
        int r = warp_m * 32 + mt * 16 + (lane & 15);
        int c = (lane >> 4) * 8;
        aRel[mt] = OAH + r * 80 + c * 2;
    }
    uint32_t bRel[4];
    #pragma unroll
    for (int ntp = 0; ntp < 4; ntp++) {
        int n = warp_n * 64 + ntp * 16 + (lane >> 4) * 8 + (lane & 7);
        int c = ((lane >> 3) & 1) * 8;
        bRel[ntp] = OBH + n * 80 + c * 2;
    }
    const uint32_t dL = OAL - OAH;

    ISSUE_FILL(0, 0);
    CP_COMMIT();

    const int nkt = KK / KT;
    #pragma unroll
    for (int kt = 0; kt < nkt; kt++) {
        if (kt + 1 < nkt) {
            ISSUE_FILL((kt + 1) & 1, (kt + 1) * KT);
            CP_COMMIT();
            CP_WAIT1();
        } else {
            CP_WAIT0();
        }
        __syncthreads();

        uint32_t stg = sb + (kt & 1) * STG;
        #pragma unroll
        for (int ksub = 0; ksub < 2; ksub++) {
            uint32_t koff = ksub * 32;
            uint32_t aH[2][4], aLr[2][4];
            #pragma unroll
            for (int mt = 0; mt < 2; mt++) {
                ldmx4(aH[mt],  stg + aRel[mt] + koff);
                ldmx4(aLr[mt], stg + aRel[mt] + koff + dL);
            }
            {
                uint32_t bH[8][2];
                #pragma unroll
                for (int ntp = 0; ntp < 4; ntp++) {
                    uint32_t t[4];
                    ldmx4(t, stg + bRel[ntp] + koff);
                    bH[2*ntp][0] = t[0]; bH[2*ntp][1] = t[1];
                    bH[2*ntp+1][0] = t[2]; bH[2*ntp+1][1] = t[3];
                }
                #pragma unroll
                for (int mt = 0; mt < 2; mt++)
                    #pragma unroll
                    for (int nt = 0; nt < 8; nt++)
                        mma_bf16(acc[mt][nt], aH[mt], bH[nt]);
                #pragma unroll
                for (int mt = 0; mt < 2; mt++)
                    #pragma unroll
                    for (int nt = 0; nt < 8; nt++)
                        mma_bf16(acc[mt][nt], aLr[mt], bH[nt]);
            }
            {
                uint32_t bL[8][2];
                #pragma unroll
                for (int ntp = 0; ntp < 4; ntp++) {
                    uint32_t t[4];
                    ldmx4(t, stg + bRel[ntp] + koff + dL);
                    bL[2*ntp][0] = t[0]; bL[2*ntp][1] = t[1];
                    bL[2*ntp+1][0] = t[2]; bL[2*ntp+1][1] = t[3];
                }
                #pragma unroll
                for (int mt = 0; mt < 2; mt++)
                    #pragma unroll
                    for (int nt = 0; nt < 8; nt++)
                        mma_bf16(acc[mt][nt], aH[mt], bL[nt]);
            }
        }
        __syncthreads();
    }
#undef ISSUE_FILL

    // ---- epilogue ----
    const float bnmul = rsqrtf(1.0f + 1e-5f);
    #pragma unroll
    for (int nt = 0; nt < 8; nt++) {
        int col0 = colBase + warp_n * 64 + nt * 8 + 2 * tg;
        float b0 = __ldg(&bias[col0]);
        float b1 = __ldg(&bias[col0 + 1]);
        float g0 = 0.f, g1 = 0.f, be0 = 0.f, be1 = 0.f;
        if (BN_OUT) {
            g0 = __ldg(&gamma[col0]) * bnmul;     be0 = __ldg(&beta[col0]);
            g1 = __ldg(&gamma[col0 + 1]) * bnmul; be1 = __ldg(&beta[col0 + 1]);
        }
        #pragma unroll
        for (int mt = 0; mt < 2; mt++) {
            int r0 = rowBase + warp_m * 32 + mt * 16 + g;
            #pragma unroll
            for (int half = 0; half < 2; half++) {
                int row = r0 + half * 8;
                if (row < N) {
                    float v0 = fmaxf(acc[mt][nt][2 * half + 0] + b0, 0.f);
                    float v1 = fmaxf(acc[mt][nt][2 * half + 1] + b1, 0.f);
                    if (BN_OUT) { v0 = v0 * g0 + be0; v1 = v1 * g1 + be1; }
                    if (EPI_LIMB) {
                        float h0,l0,h1,l1;
                        split2(v0, h0, l0); split2(v1, h1, l1);
                        *(uint32_t*)&CH[(size_t)row * M + col0] = pkbf(h0, h1);
                        *(uint32_t*)&CL[(size_t)row * M + col0] = pkbf(l0, l1);
                    } else {
                        *(float2*)(Cf + (size_t)row * M + col0) = make_float2(v0, v1);
                    }
                }
            }
        }
    }
}

// ---------------- fused pooling + head (one block per graph) ----------------
__device__ __forceinline__ int lbound(const int* a, int n, int v) {
    int lo = 0, hi = n;
    while (lo < hi) { int m = (lo + hi) >> 1; if (a[m] < v) lo = m + 1; else hi = m; }
    return lo;
}

__global__ void poolhead_k(const float* __restrict__ H, const int* __restrict__ batch,
                           const float* __restrict__ lw1, const float* __restrict__ lb1,
                           const float* __restrict__ lw2, const float* __restrict__ lb2,
                           float* __restrict__ out)
{
    int g = blockIdx.x;
    int t = threadIdx.x;
    __shared__ int ss, se;
    if (t == 0)  ss = lbound(batch, N_NODES, g);
    if (t == 32) se = lbound(batch, N_NODES, g + 1);
    __syncthreads();
    int start = ss, end = se;
    int c = t & 63, sub = t >> 6;
    const float4* h4 = (const float4*)H;
    float4 acc = make_float4(0.f, 0.f, 0.f, 0.f);
    for (int i = start + sub; i < end; i += 4) {
        float4 v = h4[(size_t)i * 64 + c];
        acc.x += v.x; acc.y += v.y; acc.z += v.z; acc.w += v.w;
    }
    __shared__ float4 red[256];
    red[t] = acc;
    __syncthreads();
    __shared__ float p[HID];
    if (sub == 0) {
        float4 a = red[c], b = red[c + 64], c2 = red[c + 128], d = red[c + 192];
        int cnt = end - start;
        float inv = 1.0f / (float)(cnt > 1 ? cnt : 1);
        p[c * 4 + 0] = (a.x + b.x + c2.x + d.x) * inv;
        p[c * 4 + 1] = (a.y + b.y + c2.y + d.y) * inv;
        p[c * 4 + 2] = (a.z + b.z + c2.z + d.z) * inv;
        p[c * 4 + 3] = (a.w + b.w + c2.w + d.w) * inv;
    }
    __syncthreads();
    __shared__ float o1[HID], o2[OUT_DIM];
    __shared__ float s_m, s_l;
    float accv = __ldg(&lb1[t]);
    for (int k = 0; k < HID; k++) accv = fmaf(p[k], __ldg(&lw1[k * HID + t]), accv);
    o1[t] = fmaxf(accv, 0.f);
    __syncthreads();
    if (t < OUT_DIM) {
        float a = __ldg(&lb2[t]);
        for (int k = 0; k < HID; k++) a = fmaf(o1[k], __ldg(&lw2[k * OUT_DIM + t]), a);
        o2[t] = a;
    }
    __syncthreads();
    if (t == 0) {
        float m = -1e30f;
        for (int j = 0; j < OUT_DIM; j++) m = fmaxf(m, o2[j]);
        float s = 0.f;
        for (int j = 0; j < OUT_DIM; j++) s += expf(o2[j] - m);
        s_m = m; s_l = logf(s);
    }
    __syncthreads();
    if (t < OUT_DIM) out[g * OUT_DIM + t] = o2[t] - s_m - s_l;
}

// ---------------- launcher ----------------
extern "C" void kernel_launch(void* const* d_in, const int* in_sizes, int n_in,
                              void* d_out, int out_size)
{
    const float* x    = (const float*)d_in[0];
    const int*   ei   = (const int*)  d_in[1];
    const int*   batch= (const int*)  d_in[2];
    const float* w1a  = (const float*)d_in[3];
    const float* b1a  = (const float*)d_in[4];
    const float* w2a  = (const float*)d_in[5];
    const float* b2a  = (const float*)d_in[6];
    const float* ga   = (const float*)d_in[7];
    const float* bba  = (const float*)d_in[8];
    const float* eps0 = (const float*)d_in[9];
    const float* w1r  = (const float*)d_in[10];
    const float* b1r  = (const float*)d_in[11];
    const float* w2r  = (const float*)d_in[12];
    const float* b2r  = (const float*)d_in[13];
    const float* gr   = (const float*)d_in[14];
    const float* br   = (const float*)d_in[15];
    const float* epsr = (const float*)d_in[16];
    const float* lw1  = (const float*)d_in[17];
    const float* lb1  = (const float*)d_in[18];
    const float* lw2  = (const float*)d_in[19];
    const float* lb2  = (const float*)d_in[20];
    float* out = (float*)d_out;

    const int* src = ei;
    const int* dst = ei + N_EDGES;

    void *hA_p, *hB_p, *AH_p, *AL_p, *TH_p, *TL_p, *WH_p, *WL_p;
    void *deg_p, *rp_p, *cur_p;
    cudaGetSymbolAddress(&hA_p, g_hA);
    cudaGetSymbolAddress(&hB_p, g_hB);
    cudaGetSymbolAddress(&AH_p, g_AH);
    cudaGetSymbolAddress(&AL_p, g_AL);
    cudaGetSymbolAddress(&TH_p, g_TH);
    cudaGetSymbolAddress(&TL_p, g_TL);
    cudaGetSymbolAddress(&WH_p, g_WH);
    cudaGetSymbolAddress(&WL_p, g_WL);
    cudaGetSymbolAddress(&deg_p, g_deg);
    cudaGetSymbolAddress(&rp_p,  g_rowptr);
    cudaGetSymbolAddress(&cur_p, g_cursor);

    float* hA = (float*)hA_p;
    float* hB = (float*)hB_p;
    __nv_bfloat16* AH = (__nv_bfloat16*)AH_p;
    __nv_bfloat16* AL = (__nv_bfloat16*)AL_p;
    __nv_bfloat16* TH = (__nv_bfloat16*)TH_p;
    __nv_bfloat16* TL = (__nv_bfloat16*)TL_p;
    __nv_bfloat16* WH = (__nv_bfloat16*)WH_p;
    __nv_bfloat16* WL = (__nv_bfloat16*)WL_p;

    static bool attr_done = false;
    if (!attr_done) {
        cudaFuncSetAttribute(gemm_p<128, true,  false>,
                             cudaFuncAttributeMaxDynamicSharedMemorySize, GSMEM);
        cudaFuncSetAttribute(gemm_p<256, true,  false>,
                             cudaFuncAttributeMaxDynamicSharedMemorySize, GSMEM);
        cudaFuncSetAttribute(gemm_p<256, false, true>,
                             cudaFuncAttributeMaxDynamicSharedMemorySize, GSMEM);
        attr_done = true;
    }

    // --- weight pre-split/transpose (single fused launch) ---
    wt_all<<<(W_TOTAL + 255) / 256, 256>>>(w1a, w2a, w1r, w2r, WH, WL);

    // --- CSR build ---
    cudaMemsetAsync(deg_p, 0, N_NODES * sizeof(int));
    hist_k<<<(N_EDGES + 255) / 256, 256>>>(dst);
    scan_k<<<1, 1024>>>();
    cudaMemcpyAsync(cur_p, rp_p, N_NODES * sizeof(int), cudaMemcpyDeviceToDevice);
    fill_k<<<(N_EDGES + 255) / 256, 256>>>(src, dst);

    const int OW1A = 0;
    const int OW2A = 32768;
    const int OW1R = 98304;
    const int OW2R = 294912;

    dim3 grid(HID / 128, (N_NODES + 127) / 128);   // (2, 391)

    // --- layer 1 ---
    aggf_k<<<(N_NODES * 32) / 256, 256>>>(x, eps0, IN_DIM / 4, AH, AL);
    gemm_p<128, true,  false><<<grid, 256, GSMEM>>>(AH, AL, WH + OW1A, WL + OW1A,
                                                    b1a, nullptr, nullptr,
                                                    nullptr, TH, TL, N_NODES, HID);
    gemm_p<256, false, true ><<<grid, 256, GSMEM>>>(TH, TL, WH + OW2A, WL + OW2A,
                                                    b2a, ga, bba,
                                                    hA, nullptr, nullptr, N_NODES, HID);

    // --- layers 2..4 ---
    const float* hin = hA;
    float* hout = hB;
    for (int i = 0; i < 3; i++) {
        aggf_k<<<(N_NODES * 64) / 256, 256>>>(hin, epsr + i, HID / 4, AH, AL);
        gemm_p<256, true,  false><<<grid, 256, GSMEM>>>(AH, AL,
                                                        WH + OW1R + i * 65536,
                                                        WL + OW1R + i * 65536,
                                                        b1r + i * HID, nullptr, nullptr,
                                                        nullptr, TH, TL, N_NODES, HID);
        gemm_p<256, false, true ><<<grid, 256, GSMEM>>>(TH, TL,
                                                        WH + OW2R + i * 65536,
                                                        WL + OW2R + i * 65536,
                                                        b2r + i * HID,
                                                        gr + i * HID, br + i * HID,
                                                        hout, nullptr, nullptr,
                                                        N_NODES, HID);
        const float* t2 = hin; hin = hout; hout = (float*)t2;
    }

    // --- fused pooling + head ---
    poolhead_k<<<N_GRAPHS, 256>>>(hin, batch, lw1, lb1, lw2, lb2, out);
}

// round 13
// speedup vs baseline: 1.1844x; 1.0793x over previous
#include <cuda_runtime.h>
#include <cuda_bf16.h>
#include <math.h>
#include <stdint.h>

#define N_NODES  50000
#define N_EDGES  800000
#define N_GRAPHS 512
#define IN_DIM   128
#define HID      256
#define OUT_DIM  40
#define SCAN_B   512
#define N_SBLK   ((N_NODES + SCAN_B - 1) / SCAN_B)   // 98

// ---------------- scratch (device globals; no allocation allowed) ----------------
__device__ float g_hA [(size_t)N_NODES * HID];
__device__ float g_hB [(size_t)N_NODES * HID];
__device__ __nv_bfloat16 g_AH[(size_t)N_NODES * HID];
__device__ __nv_bfloat16 g_AL[(size_t)N_NODES * HID];
__device__ __nv_bfloat16 g_TH[(size_t)N_NODES * HID];
__device__ __nv_bfloat16 g_TL[(size_t)N_NODES * HID];
#define W_TOTAL 491520   // 256x128 + 7x 256x256, transposed K-major
__device__ __nv_bfloat16 g_WH[W_TOTAL];
__device__ __nv_bfloat16 g_WL[W_TOTAL];
__device__ int   g_deg[N_NODES];
__device__ int   g_rowptr[N_NODES + 1];
__device__ int   g_cursor[N_NODES];
__device__ int   g_eidx[N_EDGES];
__device__ int   g_bsum[N_SBLK];
__device__ int   g_boff[N_SBLK];

// ---------------- helpers ----------------
__device__ __forceinline__ uint32_t pkbf(float a, float b) {
    __nv_bfloat162 t = __floats2bfloat162_rn(a, b);
    uint32_t u; memcpy(&u, &t, 4); return u;
}
__device__ __forceinline__ void split2(float v, float& h, float& l) {
    h = __bfloat162float(__float2bfloat16(v));
    l = v - h;
}
__device__ __forceinline__ uint32_t s2u(const void* p) {
    uint32_t a;
    asm("{ .reg .u64 t; cvta.to.shared.u64 t, %1; cvt.u32.u64 %0, t; }"
        : "=r"(a) : "l"(p));
    return a;
}
__device__ __forceinline__ void ldmx4(uint32_t* r, uint32_t addr) {
    asm volatile("ldmatrix.sync.aligned.m8n8.x4.shared.b16 {%0,%1,%2,%3}, [%4];"
                 : "=r"(r[0]), "=r"(r[1]), "=r"(r[2]), "=r"(r[3]) : "r"(addr));
}
__device__ __forceinline__ void mma_bf16(float* c, const uint32_t* a, const uint32_t* b) {
    asm volatile(
        "mma.sync.aligned.m16n8k16.row.col.f32.bf16.bf16.f32 "
        "{%0,%1,%2,%3}, {%4,%5,%6,%7}, {%8,%9}, {%0,%1,%2,%3};"
        : "+f"(c[0]), "+f"(c[1]), "+f"(c[2]), "+f"(c[3])
        : "r"(a[0]), "r"(a[1]), "r"(a[2]), "r"(a[3]), "r"(b[0]), "r"(b[1]));
}
__device__ __forceinline__ void cpa16(uint32_t dst, const void* src, uint32_t vsz) {
    asm volatile("cp.async.cg.shared.global [%0], [%1], 16, %2;"
                 :: "r"(dst), "l"(src), "r"(vsz));
}
#define CP_COMMIT() asm volatile("cp.async.commit_group;" ::: "memory")
#define CP_WAIT1()  asm volatile("cp.async.wait_group 1;" ::: "memory")
#define CP_WAIT0()  asm volatile("cp.async.wait_group 0;" ::: "memory")

// ---------------- CSR build ----------------
__global__ void hist_k(const int* __restrict__ dst) {
    int e2 = (blockIdx.x * blockDim.x + threadIdx.x) * 2;
    if (e2 < N_EDGES) {
        int2 d = *(const int2*)(dst + e2);
        atomicAdd(&g_deg[d.x], 1);
        atomicAdd(&g_deg[d.y], 1);
    }
}

// phase 1: per-block local exclusive scan + block sums
__global__ void scan1_k() {
    __shared__ int buf[SCAN_B];
    int base = blockIdx.x * SCAN_B;
    int tid = threadIdx.x;
    int v = (base + tid < N_NODES) ? g_deg[base + tid] : 0;
    buf[tid] = v;
    __syncthreads();
    #pragma unroll
    for (int off = 1; off < SCAN_B; off <<= 1) {
        int t = (tid >= off) ? buf[tid - off] : 0;
        __syncthreads();
        buf[tid] += t;
        __syncthreads();
    }
    if (base + tid < N_NODES) g_rowptr[base + tid] = buf[tid] - v;
    if (tid == SCAN_B - 1) g_bsum[blockIdx.x] = buf[tid];
}

// phase 2: exclusive scan of the 98 block sums (one small block)
__global__ void scan2_k() {
    __shared__ int buf[128];
    int tid = threadIdx.x;
    int v = (tid < N_SBLK) ? g_bsum[tid] : 0;
    buf[tid] = v;
    __syncthreads();
    #pragma unroll
    for (int off = 1; off < 128; off <<= 1) {
        int t = (tid >= off) ? buf[tid - off] : 0;
        __syncthreads();
        buf[tid] += t;
        __syncthreads();
    }
    if (tid < N_SBLK) g_boff[tid] = buf[tid] - v;
}

// phase 3: add block offsets, write cursor copy, finalize rowptr[N]
__global__ void scan3_k() {
    int i = blockIdx.x * blockDim.x + threadIdx.x;
    if (i < N_NODES) {
        int r = g_rowptr[i] + g_boff[i / SCAN_B];
        g_rowptr[i] = r;
        g_cursor[i] = r;
    }
    if (i == 0) g_rowptr[N_NODES] = N_EDGES;  // every edge lands in [0,N)
}

__global__ void fill_k(const int* __restrict__ src, const int* __restrict__ dst) {
    int e2 = (blockIdx.x * blockDim.x + threadIdx.x) * 2;
    if (e2 < N_EDGES) {
        int2 d = *(const int2*)(dst + e2);
        int2 s = *(const int2*)(src + e2);
        int p0 = atomicAdd(&g_cursor[d.x], 1);
        g_eidx[p0] = s.x;
        int p1 = atomicAdd(&g_cursor[d.y], 1);
        g_eidx[p1] = s.y;
    }
}

// ---------------- fused weight pre-split + transpose (all 8 matrices) ----------------
__global__ void wt_all(const float* __restrict__ w1a, const float* __restrict__ w2a,
                       const float* __restrict__ w1r, const float* __restrict__ w2r,
                       __nv_bfloat16* __restrict__ dH, __nv_bfloat16* __restrict__ dL) {
    int idx = blockIdx.x * blockDim.x + threadIdx.x;
    if (idx >= W_TOTAL) return;
    const float* W; int K, loc;
    if (idx < 32768)       { W = w1a; K = 128; loc = idx; }
    else if (idx < 98304)  { W = w2a; K = 256; loc = idx - 32768; }
    else if (idx < 294912) { int r = idx - 98304;  W = w1r + (r >> 16) * 65536; K = 256; loc = r & 65535; }
    else                   { int r = idx - 294912; W = w2r + (r >> 16) * 65536; K = 256; loc = r & 65535; }
    int n = loc / K, k = loc - n * K;
    float v = __ldg(&W[(size_t)k * HID + n]);
    float h, l; split2(v, h, l);
    dH[idx] = __float2bfloat16(h);
    dL[idx] = __float2bfloat16(l);
}

// ---------------- fused aggregation + GIN add + limb split ----------------
__global__ void aggf_k(const float* __restrict__ X, const float* __restrict__ epsp,
                       int D4, __nv_bfloat16* __restrict__ AH,
                       __nv_bfloat16* __restrict__ AL) {
    int gid  = blockIdx.x * blockDim.x + threadIdx.x;
    int node = gid / D4;
    int c    = gid - node * D4;
    int s = g_rowptr[node];
    int e = g_rowptr[node + 1];
    const float4* x4 = (const float4*)X;
    float4 acc0 = make_float4(0.f, 0.f, 0.f, 0.f);
    float4 acc1 = make_float4(0.f, 0.f, 0.f, 0.f);
    int j = s;
    for (; j + 1 < e; j += 2) {
        int s0 = g_eidx[j];
        int s1 = g_eidx[j + 1];
        float4 v0 = __ldg(&x4[(size_t)s0 * D4 + c]);
        float4 v1 = __ldg(&x4[(size_t)s1 * D4 + c]);
        acc0.x += v0.x; acc0.y += v0.y; acc0.z += v0.z; acc0.w += v0.w;
        acc1.x += v1.x; acc1.y += v1.y; acc1.z += v1.z; acc1.w += v1.w;
    }
    if (j < e) {
        int s0 = g_eidx[j];
        float4 v0 = __ldg(&x4[(size_t)s0 * D4 + c]);
        acc0.x += v0.x; acc0.y += v0.y; acc0.z += v0.z; acc0.w += v0.w;
    }
    float alpha = 1.0f + __ldg(epsp);
    float4 xs = __ldg(&x4[(size_t)node * D4 + c]);
    float4 v;
    v.x = alpha * xs.x + acc0.x + acc1.x;
    v.y = alpha * xs.y + acc0.y + acc1.y;
    v.z = alpha * xs.z + acc0.z + acc1.z;
    v.w = alpha * xs.w + acc0.w + acc1.w;
    float h0,l0,h1,l1,h2,l2,h3,l3;
    split2(v.x,h0,l0); split2(v.y,h1,l1); split2(v.z,h2,l2); split2(v.w,h3,l3);
    size_t base = (size_t)node * (D4 * 4) + c * 4;
    *(uint2*)&AH[base] = make_uint2(pkbf(h0, h1), pkbf(h2, h3));
    *(uint2*)&AL[base] = make_uint2(pkbf(l0, l1), pkbf(l2, l3));
}

// ---------------- pipelined bf16 2-limb tensor GEMM (occ 2, K templated) ----------
#define KT 32
#define OAH 0u
#define OAL 10240u
#define OBH 20480u
#define OBL 30720u
#define STG 40960u
#define GSMEM (2 * STG)

template<int KK, bool EPI_LIMB, bool BN_OUT>
__global__ void __launch_bounds__(256, 2) gemm_p(
    const __nv_bfloat16* __restrict__ AH, const __nv_bfloat16* __restrict__ AL,
    const __nv_bfloat16* __restrict__ WH, const __nv_bfloat16* __restrict__ WL,
    const float* __restrict__ bias,
    const float* __restrict__ gamma, const float* __restrict__ beta,
    float* __restrict__ Cf, __nv_bfloat16* __restrict__ CH,
    __nv_bfloat16* __restrict__ CL,
    int N, int M)
{
    extern __shared__ char smem[];
    uint32_t sb = s2u(smem);
    int tid = threadIdx.x;
    int lane = tid & 31;
    int wid  = tid >> 5;
    int warp_m = wid & 3;
    int warp_n = wid >> 2;
    int g  = lane >> 2;
    int tg = lane & 3;

    int rowBase = blockIdx.y * 128;
    int colBase = blockIdx.x * 128;

    int fr = tid >> 1;
    int fk = (tid & 1) * 16;
    bool avalid = (rowBase + fr) < N;
    size_t aBase = (size_t)(avalid ? (rowBase + fr) : 0) * KK + fk;
    size_t bBase = (size_t)(colBase + fr) * KK + fk;
    uint32_t avsz = avalid ? 16u : 0u;
    uint32_t aDst = fr * 80 + fk * 2;

#define ISSUE_FILL(stage, k0) do {                                      \
    uint32_t s_ = sb + (stage) * STG;                                   \
    const char* pAH = (const char*)(AH + aBase + (k0));                 \
    const char* pAL = (const char*)(AL + aBase + (k0));                 \
    cpa16(s_ + OAH + aDst,      pAH,      avsz);                        \
    cpa16(s_ + OAH + aDst + 16, pAH + 16, avsz);                        \
    cpa16(s_ + OAL + aDst,      pAL,      avsz);                        \
    cpa16(s_ + OAL + aDst + 16, pAL + 16, avsz);                        \
    const char* pBH = (const char*)(WH + bBase + (k0));                 \
    const char* pBL = (const char*)(WL + bBase + (k0));                 \
    cpa16(s_ + OBH + aDst,      pBH,      16u);                         \
    cpa16(s_ + OBH + aDst + 16, pBH + 16, 16u);                         \
    cpa16(s_ + OBL + aDst,      pBL,      16u);                         \
    cpa16(s_ + OBL + aDst + 16, pBL + 16, 16u);                         \
} while (0)

    float acc[2][8][4];
    #pragma unroll
    for (int mt = 0; mt < 2; mt++)
        #pragma unroll
        for (int nt = 0; nt < 8; nt++)
            #pragma unroll
            for (int q = 0; q < 4; q++) acc[mt][nt][q] = 0.f;

    uint32_t aRel[2];
    #pragma unroll
    for (int mt = 0; mt < 2; mt++) {
        int r = warp_m * 32 + mt * 16 + (lane & 15);
        int c = (lane >> 4) * 8;
        aRel[mt] = OAH + r * 80 + c * 2;
    }
    uint32_t bRel[4];
    #pragma unroll
    for (int ntp = 0; ntp < 4; ntp++) {
        int n = warp_n * 64 + ntp * 16 + (lane >> 4) * 8 + (lane & 7);
        int c = ((lane >> 3) & 1) * 8;
        bRel[ntp] = OBH + n * 80 + c * 2;
    }
    const uint32_t dL = OAL - OAH;

    ISSUE_FILL(0, 0);
    CP_COMMIT();

    const int nkt = KK / KT;
    #pragma unroll
    for (int kt = 0; kt < nkt; kt++) {
        if (kt + 1 < nkt) {
            ISSUE_FILL((kt + 1) & 1, (kt + 1) * KT);
            CP_COMMIT();
            CP_WAIT1();
        } else {
            CP_WAIT0();
        }
        __syncthreads();

        uint32_t stg = sb + (kt & 1) * STG;
        #pragma unroll
        for (int ksub = 0; ksub < 2; ksub++) {
            uint32_t koff = ksub * 32;
            uint32_t aH[2][4], aLr[2][4];
            #pragma unroll
            for (int mt = 0; mt < 2; mt++) {
                ldmx4(aH[mt],  stg + aRel[mt] + koff);
                ldmx4(aLr[mt], stg + aRel[mt] + koff + dL);
            }
            {
                uint32_t bH[8][2];
                #pragma unroll
                for (int ntp = 0; ntp < 4; ntp++) {
                    uint32_t t[4];
                    ldmx4(t, stg + bRel[ntp] + koff);
                    bH[2*ntp][0] = t[0]; bH[2*ntp][1] = t[1];
                    bH[2*ntp+1][0] = t[2]; bH[2*ntp+1][1] = t[3];
                }
                #pragma unroll
                for (int mt = 0; mt < 2; mt++)
                    #pragma unroll
                    for (int nt = 0; nt < 8; nt++)
                        mma_bf16(acc[mt][nt], aH[mt], bH[nt]);
                #pragma unroll
                for (int mt = 0; mt < 2; mt++)
                    #pragma unroll
                    for (int nt = 0; nt < 8; nt++)
                        mma_bf16(acc[mt][nt], aLr[mt], bH[nt]);
            }
            {
                uint32_t bL[8][2];
                #pragma unroll
                for (int ntp = 0; ntp < 4; ntp++) {
                    uint32_t t[4];
                    ldmx4(t, stg + bRel[ntp] + koff + dL);
                    bL[2*ntp][0] = t[0]; bL[2*ntp][1] = t[1];
                    bL[2*ntp+1][0] = t[2]; bL[2*ntp+1][1] = t[3];
                }
                #pragma unroll
                for (int mt = 0; mt < 2; mt++)
                    #pragma unroll
                    for (int nt = 0; nt < 8; nt++)
                        mma_bf16(acc[mt][nt], aH[mt], bL[nt]);
            }
        }
        __syncthreads();
    }
#undef ISSUE_FILL

    // ---- epilogue ----
    const float bnmul = rsqrtf(1.0f + 1e-5f);
    #pragma unroll
    for (int nt = 0; nt < 8; nt++) {
        int col0 = colBase + warp_n * 64 + nt * 8 + 2 * tg;
        float b0 = __ldg(&bias[col0]);
        float b1 = __ldg(&bias[col0 + 1]);
        float g0 = 0.f, g1 = 0.f, be0 = 0.f, be1 = 0.f;
        if (BN_OUT) {
            g0 = __ldg(&gamma[col0]) * bnmul;     be0 = __ldg(&beta[col0]);
            g1 = __ldg(&gamma[col0 + 1]) * bnmul; be1 = __ldg(&beta[col0 + 1]);
        }
        #pragma unroll
        for (int mt = 0; mt < 2; mt++) {
            int r0 = rowBase + warp_m * 32 + mt * 16 + g;
            #pragma unroll
            for (int half = 0; half < 2; half++) {
                int row = r0 + half * 8;
                if (row < N) {
                    float v0 = fmaxf(acc[mt][nt][2 * half + 0] + b0, 0.f);
                    float v1 = fmaxf(acc[mt][nt][2 * half + 1] + b1, 0.f);
                    if (BN_OUT) { v0 = v0 * g0 + be0; v1 = v1 * g1 + be1; }
                    if (EPI_LIMB) {
                        float h0,l0,h1,l1;
                        split2(v0, h0, l0); split2(v1, h1, l1);
                        *(uint32_t*)&CH[(size_t)row * M + col0] = pkbf(h0, h1);
                        *(uint32_t*)&CL[(size_t)row * M + col0] = pkbf(l0, l1);
                    } else {
                        *(float2*)(Cf + (size_t)row * M + col0) = make_float2(v0, v1);
                    }
                }
            }
        }
    }
}

// ---------------- fused pooling + head (one block per graph) ----------------
__device__ __forceinline__ int lbound(const int* a, int n, int v) {
    int lo = 0, hi = n;
    while (lo < hi) { int m = (lo + hi) >> 1; if (a[m] < v) lo = m + 1; else hi = m; }
    return lo;
}

__global__ void poolhead_k(const float* __restrict__ H, const int* __restrict__ batch,
                           const float* __restrict__ lw1, const float* __restrict__ lb1,
                           const float* __restrict__ lw2, const float* __restrict__ lb2,
                           float* __restrict__ out)
{
    int g = blockIdx.x;
    int t = threadIdx.x;
    __shared__ int ss, se;
    if (t == 0)  ss = lbound(batch, N_NODES, g);
    if (t == 32) se = lbound(batch, N_NODES, g + 1);
    __syncthreads();
    int start = ss, end = se;
    int c = t & 63, sub = t >> 6;
    const float4* h4 = (const float4*)H;
    float4 acc = make_float4(0.f, 0.f, 0.f, 0.f);
    for (int i = start + sub; i < end; i += 4) {
        float4 v = h4[(size_t)i * 64 + c];
        acc.x += v.x; acc.y += v.y; acc.z += v.z; acc.w += v.w;
    }
    __shared__ float4 red[256];
    red[t] = acc;
    __syncthreads();
    __shared__ float p[HID];
    if (sub == 0) {
        float4 a = red[c], b = red[c + 64], c2 = red[c + 128], d = red[c + 192];
        int cnt = end - start;
        float inv = 1.0f / (float)(cnt > 1 ? cnt : 1);
        p[c * 4 + 0] = (a.x + b.x + c2.x + d.x) * inv;
        p[c * 4 + 1] = (a.y + b.y + c2.y + d.y) * inv;
        p[c * 4 + 2] = (a.z + b.z + c2.z + d.z) * inv;
        p[c * 4 + 3] = (a.w + b.w + c2.w + d.w) * inv;
    }
    __syncthreads();
    __shared__ float o1[HID], o2[OUT_DIM];
    __shared__ float s_m, s_l;
    float accv = __ldg(&lb1[t]);
    for (int k = 0; k < HID; k++) accv = fmaf(p[k], __ldg(&lw1[k * HID + t]), accv);
    o1[t] = fmaxf(accv, 0.f);
    __syncthreads();
    if (t < OUT_DIM) {
        float a = __ldg(&lb2[t]);
        for (int k = 0; k < HID; k++) a = fmaf(o1[k], __ldg(&lw2[k * OUT_DIM + t]), a);
        o2[t] = a;
    }
    __syncthreads();
    if (t == 0) {
        float m = -1e30f;
        for (int j = 0; j < OUT_DIM; j++) m = fmaxf(m, o2[j]);
        float s = 0.f;
        for (int j = 0; j < OUT_DIM; j++) s += expf(o2[j] - m);
        s_m = m; s_l = logf(s);
    }
    __syncthreads();
    if (t < OUT_DIM) out[g * OUT_DIM + t] = o2[t] - s_m - s_l;
}

// ---------------- launcher ----------------
extern "C" void kernel_launch(void* const* d_in, const int* in_sizes, int n_in,
                              void* d_out, int out_size)
{
    const float* x    = (const float*)d_in[0];
    const int*   ei   = (const int*)  d_in[1];
    const int*   batch= (const int*)  d_in[2];
    const float* w1a  = (const float*)d_in[3];
    const float* b1a  = (const float*)d_in[4];
    const float* w2a  = (const float*)d_in[5];
    const float* b2a  = (const float*)d_in[6];
    const float* ga   = (const float*)d_in[7];
    const float* bba  = (const float*)d_in[8];
    const float* eps0 = (const float*)d_in[9];
    const float* w1r  = (const float*)d_in[10];
    const float* b1r  = (const float*)d_in[11];
    const float* w2r  = (const float*)d_in[12];
    const float* b2r  = (const float*)d_in[13];
    const float* gr   = (const float*)d_in[14];
    const float* br   = (const float*)d_in[15];
    const float* epsr = (const float*)d_in[16];
    const float* lw1  = (const float*)d_in[17];
    const float* lb1  = (const float*)d_in[18];
    const float* lw2  = (const float*)d_in[19];
    const float* lb2  = (const float*)d_in[20];
    float* out = (float*)d_out;

    const int* src = ei;
    const int* dst = ei + N_EDGES;

    void *hA_p, *hB_p, *AH_p, *AL_p, *TH_p, *TL_p, *WH_p, *WL_p, *deg_p;
    cudaGetSymbolAddress(&hA_p, g_hA);
    cudaGetSymbolAddress(&hB_p, g_hB);
    cudaGetSymbolAddress(&AH_p, g_AH);
    cudaGetSymbolAddress(&AL_p, g_AL);
    cudaGetSymbolAddress(&TH_p, g_TH);
    cudaGetSymbolAddress(&TL_p, g_TL);
    cudaGetSymbolAddress(&WH_p, g_WH);
    cudaGetSymbolAddress(&WL_p, g_WL);
    cudaGetSymbolAddress(&deg_p, g_deg);

    float* hA = (float*)hA_p;
    float* hB = (float*)hB_p;
    __nv_bfloat16* AH = (__nv_bfloat16*)AH_p;
    __nv_bfloat16* AL = (__nv_bfloat16*)AL_p;
    __nv_bfloat16* TH = (__nv_bfloat16*)TH_p;
    __nv_bfloat16* TL = (__nv_bfloat16*)TL_p;
    __nv_bfloat16* WH = (__nv_bfloat16*)WH_p;
    __nv_bfloat16* WL = (__nv_bfloat16*)WL_p;

    static bool attr_done = false;
    if (!attr_done) {
        cudaFuncSetAttribute(gemm_p<128, true,  false>,
                             cudaFuncAttributeMaxDynamicSharedMemorySize, GSMEM);
        cudaFuncSetAttribute(gemm_p<256, true,  false>,
                             cudaFuncAttributeMaxDynamicSharedMemorySize, GSMEM);
        cudaFuncSetAttribute(gemm_p<256, false, true>,
                             cudaFuncAttributeMaxDynamicSharedMemorySize, GSMEM);
        attr_done = true;
    }

    // --- weight pre-split/transpose (single fused launch) ---
    wt_all<<<(W_TOTAL + 255) / 256, 256>>>(w1a, w2a, w1r, w2r, WH, WL);

    // --- CSR build (multi-block scan, no memcpy) ---
    cudaMemsetAsync(deg_p, 0, N_NODES * sizeof(int));
    hist_k<<<(N_EDGES / 2 + 255) / 256, 256>>>(dst);
    scan1_k<<<N_SBLK, SCAN_B>>>();
    scan2_k<<<1, 128>>>();
    scan3_k<<<(N_NODES + 255) / 256, 256>>>();
    fill_k<<<(N_EDGES / 2 + 255) / 256, 256>>>(src, dst);

    const int OW1A = 0;
    const int OW2A = 32768;
    const int OW1R = 98304;
    const int OW2R = 294912;

    dim3 grid(HID / 128, (N_NODES + 127) / 128);   // (2, 391)

    // --- layer 1 ---
    aggf_k<<<(N_NODES * 32) / 256, 256>>>(x, eps0, IN_DIM / 4, AH, AL);
    gemm_p<128, true,  false><<<grid, 256, GSMEM>>>(AH, AL, WH + OW1A, WL + OW1A,
                                                    b1a, nullptr, nullptr,
                                                    nullptr, TH, TL, N_NODES, HID);
    gemm_p<256, false, true ><<<grid, 256, GSMEM>>>(TH, TL, WH + OW2A, WL + OW2A,
                                                    b2a, ga, bba,
                                                    hA, nullptr, nullptr, N_NODES, HID);

    // --- layers 2..4 ---
    const float* hin = hA;
    float* hout = hB;
    for (int i = 0; i < 3; i++) {
        aggf_k<<<(N_NODES * 64) / 256, 256>>>(hin, epsr + i, HID / 4, AH, AL);
        gemm_p<256, true,  false><<<grid, 256, GSMEM>>>(AH, AL,
                                                        WH + OW1R + i * 65536,
                                                        WL + OW1R + i * 65536,
                                                        b1r + i * HID, nullptr, nullptr,
                                                        nullptr, TH, TL, N_NODES, HID);
        gemm_p<256, false, true ><<<grid, 256, GSMEM>>>(TH, TL,
                                                        WH + OW2R + i * 65536,
                                                        WL + OW2R + i * 65536,
                                                        b2r + i * HID,
                                                        gr + i * HID, br + i * HID,
                                                        hout, nullptr, nullptr,
                                                        N_NODES, HID);
        const float* t2 = hin; hin = hout; hout = (float*)t2;
    }

    // --- fused pooling + head ---
    poolhead_k<<<N_GRAPHS, 256>>>(hin, batch, lw1, lb1, lw2, lb2, out);
}